// round 14
// baseline (speedup 1.0000x reference)
#include <cuda_runtime.h>
#include <cuda_bf16.h>
#include <cuda_fp16.h>
#include <cstdint>
#include <cstddef>

#define SEQ 1024
#define EMB 1024
#define BATCH 4
#define NH 16
#define DH 64
#define BH (BATCH*NH)
#define SS ((size_t)SEQ*(size_t)SEQ)
#define ACT ((size_t)BATCH*SEQ*EMB)
#define EE  ((size_t)EMB*EMB)

#define SKW 20            // SMEM row stride (words): 16 data + 4 pad
#define GPLANE (128*SKW)  // one 128x32 16-bit plane (words)
#define BPLN   (64*SKW)
#define SCPLANE (2*GPLANE)
#define GBUF  (3*GPLANE)            // gemm stage: A + Wh + Wl
#define CTX2BUF (GPLANE + 2*BPLN)   // ctx stage: P + Vh + Vl

typedef __nv_bfloat16 bf16;

// ---- scratch ----
__device__ float g_V  [ACT];
__device__ float g_attn[(size_t)BH*SEQ*SEQ];        // raw masked scores (fp32)
__device__ __half g_probs[(size_t)BH*SEQ*SEQ];      // normalized probs (fp16)
__device__ __half g_qi[ACT], g_ki[ACT], g_vi[ACT];  // fp16 activations
__device__ __half g_Wq2[2*EE], g_Wk2[2*EE], g_Wv2[2*EE], g_Wo2[2*EE];  // fp16 hi/lo
__device__ __half g_Q1[ACT];                        // Q fp16 single plane (reused for ctx)
__device__ __half g_K2[2*ACT];                      // K fp16 hi/lo
__device__ __half g_Vt2[2*ACT];                     // V^T fp16 hi/lo

// ============================================================
__device__ __forceinline__ void mma16816h(float* c, const uint32_t a[4], const uint32_t b[2]){
    asm volatile("mma.sync.aligned.m16n8k16.row.col.f32.f16.f16.f32 "
        "{%0,%1,%2,%3}, {%4,%5,%6,%7}, {%8,%9}, {%0,%1,%2,%3};"
        : "+f"(c[0]), "+f"(c[1]), "+f"(c[2]), "+f"(c[3])
        : "r"(a[0]), "r"(a[1]), "r"(a[2]), "r"(a[3]), "r"(b[0]), "r"(b[1]));
}

__device__ __forceinline__ void ldsm_x4(uint32_t (&r)[4], uint32_t saddr){
    asm volatile("ldmatrix.sync.aligned.m8n8.x4.shared.b16 {%0,%1,%2,%3}, [%4];"
        : "=r"(r[0]), "=r"(r[1]), "=r"(r[2]), "=r"(r[3]) : "r"(saddr));
}

// fp16 hi/lo split of 8 floats
__device__ __forceinline__ void cvt8h(float4 x0, float4 x1, uint4& h, uint4& l){
    float x[8] = {x0.x,x0.y,x0.z,x0.w,x1.x,x1.y,x1.z,x1.w};
    __half hh[8], ll[8];
#pragma unroll
    for (int j = 0; j < 8; j++){
        hh[j] = __float2half_rn(x[j]);
        ll[j] = __float2half_rn(x[j] - __half2float(hh[j]));
    }
    h.x = (uint32_t)__half_as_ushort(hh[0]) | ((uint32_t)__half_as_ushort(hh[1])<<16);
    h.y = (uint32_t)__half_as_ushort(hh[2]) | ((uint32_t)__half_as_ushort(hh[3])<<16);
    h.z = (uint32_t)__half_as_ushort(hh[4]) | ((uint32_t)__half_as_ushort(hh[5])<<16);
    h.w = (uint32_t)__half_as_ushort(hh[6]) | ((uint32_t)__half_as_ushort(hh[7])<<16);
    l.x = (uint32_t)__half_as_ushort(ll[0]) | ((uint32_t)__half_as_ushort(ll[1])<<16);
    l.y = (uint32_t)__half_as_ushort(ll[2]) | ((uint32_t)__half_as_ushort(ll[3])<<16);
    l.z = (uint32_t)__half_as_ushort(ll[4]) | ((uint32_t)__half_as_ushort(ll[5])<<16);
    l.w = (uint32_t)__half_as_ushort(ll[6]) | ((uint32_t)__half_as_ushort(ll[7])<<16);
}

// ---- ldmatrix fp16 2-pass chunk: addresses fully hoisted ----
// aAddr/bhAddr/blAddr = buffer base + plane offset + warp tile offset + lane offset.
// All inner offsets are compile-time constants. Frag mapping validated in R8
// (bit-identical results); per-acc MMA order identical to R13 (hi then lo per ks).
template<int MT, int NT>   // NT even
__device__ __forceinline__ void mma_lds_h2(float acc[MT][NT][4],
    uint32_t aAddr, uint32_t bhAddr, uint32_t blAddr)
{
#pragma unroll
    for (int ks = 0; ks < 2; ks++){
        uint32_t bh[NT][2], bl[NT][2];
#pragma unroll
        for (int nt = 0; nt < NT/2; nt++){
            uint32_t rb[4];
            ldsm_x4(rb, bhAddr + nt*(16*SKW*4) + ks*32);
            bh[nt*2][0]=rb[0]; bh[nt*2+1][0]=rb[1];
            bh[nt*2][1]=rb[2]; bh[nt*2+1][1]=rb[3];
            ldsm_x4(rb, blAddr + nt*(16*SKW*4) + ks*32);
            bl[nt*2][0]=rb[0]; bl[nt*2+1][0]=rb[1];
            bl[nt*2][1]=rb[2]; bl[nt*2+1][1]=rb[3];
        }
#pragma unroll
        for (int mi = 0; mi < MT; mi++){
            uint32_t a[4];
            ldsm_x4(a, aAddr + mi*(16*SKW*4) + ks*32);
#pragma unroll
            for (int ni = 0; ni < NT; ni++){
                mma16816h(acc[mi][ni], a, bh[ni]);
                mma16816h(acc[mi][ni], a, bl[ni]);
            }
        }
    }
}

// per-lane ldmatrix offset: row = (g&1)*8 + (lane&7), colwords = (g>>1)*4
__device__ __forceinline__ uint32_t ldsm_laneoff(int lane){
    const int g = lane >> 3, lr = lane & 7;
    return (uint32_t)((((g & 1)*8 + lr)*SKW + (g >> 1)*4)*4);
}

__device__ __forceinline__ void store_hl_h(__half* H, size_t off, float2 v){
    __half hx = __float2half_rn(v.x), hy = __float2half_rn(v.y);
    __half2 hp; hp.x = hx; hp.y = hy;
    __half2 lp;
    lp.x = __float2half_rn(v.x - __half2float(hx));
    lp.y = __float2half_rn(v.y - __half2float(hy));
    *(__half2*)(H + off) = hp;
    *(__half2*)(H + ACT + off) = lp;
}

__device__ __forceinline__ void cp16(uint32_t dst, const void* src){
    asm volatile("cp.async.cg.shared.global [%0], [%1], 16;" :: "r"(dst), "l"(src));
}
#define CP_COMMIT() asm volatile("cp.async.commit_group;" ::: "memory")
#define CP_WAIT1()  asm volatile("cp.async.wait_group 1;" ::: "memory")

// ============================================================
// split kernels
// ============================================================
__global__ __launch_bounds__(256)
void split_act(const float* __restrict__ q, const float* __restrict__ k,
               const float* __restrict__ v,
               __half* __restrict__ qo, __half* __restrict__ ko, __half* __restrict__ vo,
               int n8)
{
    int i = blockIdx.x*blockDim.x + threadIdx.x;
    if (i >= n8) return;
    const float* src = (blockIdx.y == 0) ? q : (blockIdx.y == 1) ? k : v;
    __half* H = (blockIdx.y == 0) ? qo : (blockIdx.y == 1) ? ko : vo;
    const float* p = src + (size_t)i*8;
    float4 a = *(const float4*)p, b = *(const float4*)(p+4);
    __half2 h0 = __floats2half2_rn(a.x, a.y), h1 = __floats2half2_rn(a.z, a.w);
    __half2 h2 = __floats2half2_rn(b.x, b.y), h3 = __floats2half2_rn(b.z, b.w);
    uint4 u;
    u.x = *(uint32_t*)&h0; u.y = *(uint32_t*)&h1;
    u.z = *(uint32_t*)&h2; u.w = *(uint32_t*)&h3;
    *(uint4*)(H + (size_t)i*8) = u;
}

__global__ __launch_bounds__(256)
void split_w(const float* __restrict__ wq, const float* __restrict__ wk,
             const float* __restrict__ wv, const float* __restrict__ wo,
             __half* __restrict__ oq, __half* __restrict__ ok,
             __half* __restrict__ ov, __half* __restrict__ oo, int n8)
{
    int i = blockIdx.x*blockDim.x + threadIdx.x;
    if (i >= n8) return;
    const float* src = (blockIdx.y == 0) ? wq : (blockIdx.y == 1) ? wk :
                       (blockIdx.y == 2) ? wv : wo;
    __half* H = (blockIdx.y == 0) ? oq : (blockIdx.y == 1) ? ok :
                (blockIdx.y == 2) ? ov : oo;
    const float* p = src + (size_t)i*8;
    uint4 h, l;
    cvt8h(*(const float4*)p, *(const float4*)(p+4), h, l);
    *(uint4*)(H + (size_t)i*8) = h;
    *(uint4*)(H + EE + (size_t)i*8) = l;
}

// ============================================================
// GEMM body: fp16 2-pass, 3-stage cp.async, ldmatrix frags.
// mode 0: fp32 C; mode 1: fp16 single plane Ch; mode 2: fp16 hi/lo Ch.
// dyn smem: 3 x GBUF x 4B = 92160
// ============================================================
__device__ __forceinline__ void gemm_body(
    const __half* __restrict__ A, const __half* __restrict__ W,
    const float* __restrict__ bias, float* __restrict__ C,
    __half* __restrict__ Ch, int mode)
{
    extern __shared__ __align__(16) uint32_t smw[];
    const uint32_t sb = (uint32_t)__cvta_generic_to_shared(smw);
    const int tid = threadIdx.x, wid = tid >> 5, lane = tid & 31;
    const int wm = (wid >> 2)*64, wn = (wid & 3)*32;
    const int bm = blockIdx.y*128, bn = blockIdx.x*128;
    const int r0 = tid >> 2, s0 = tid & 3;
    const int K = EMB, N = EMB;

    float acc[4][4][4];
#pragma unroll
    for (int i = 0; i < 4; i++)
#pragma unroll
        for (int j = 0; j < 4; j++)
#pragma unroll
            for (int k = 0; k < 4; k++) acc[i][j][k] = 0.f;

    const __half* pA0 = A + (size_t)(bm + r0)*K + s0*8;
    const __half* pA1 = A + (size_t)(bm + r0 + 64)*K + s0*8;
    const __half* pW0 = W + (size_t)(bn + r0)*K + s0*8;
    const __half* pW1 = W + (size_t)(bn + r0 + 64)*K + s0*8;

    const uint32_t w0 = (r0*SKW + s0*4)*4;
    const uint32_t w1 = ((r0+64)*SKW + s0*4)*4;

    // hoisted ldmatrix lane/warp offsets
    const uint32_t lo = ldsm_laneoff(lane);
    const uint32_t aOff  = 0*GPLANE*4 + (uint32_t)(wm*SKW*4) + lo;
    const uint32_t bhOff = 1*GPLANE*4 + (uint32_t)(wn*SKW*4) + lo;
    const uint32_t blOff = 2*GPLANE*4 + (uint32_t)(wn*SKW*4) + lo;

    auto issue = [&](int c){
        uint32_t b = sb + (c % 3)*(GBUF*4);
        size_t go = (size_t)c*32;
        cp16(b + 0*GPLANE*4 + w0, pA0 + go);
        cp16(b + 0*GPLANE*4 + w1, pA1 + go);
        cp16(b + 1*GPLANE*4 + w0, pW0 + go);
        cp16(b + 1*GPLANE*4 + w1, pW1 + go);
        cp16(b + 2*GPLANE*4 + w0, pW0 + EE + go);
        cp16(b + 2*GPLANE*4 + w1, pW1 + EE + go);
        CP_COMMIT();
    };

    const int nch = K >> 5;
    issue(0);
    issue(1);
    for (int c = 0; c < nch; c++){
        CP_WAIT1();
        __syncthreads();
        if (c + 2 < nch) issue(c + 2);
        uint32_t cb = sb + (c % 3)*(GBUF*4);
        mma_lds_h2<4,4>(acc, cb + aOff, cb + bhOff, cb + blOff);
    }

    const int r = lane >> 2, cl = (lane & 3)*2;
#pragma unroll
    for (int mi = 0; mi < 4; mi++){
#pragma unroll
        for (int ni = 0; ni < 4; ni++){
            int row = bm + wm + mi*16 + r;
            int col = bn + wn + ni*8 + cl;
            float2 bv = *(const float2*)(bias + col);
            float2 o0, o1;
            o0.x = acc[mi][ni][0] + bv.x; o0.y = acc[mi][ni][1] + bv.y;
            o1.x = acc[mi][ni][2] + bv.x; o1.y = acc[mi][ni][3] + bv.y;
            if (mode == 0){
                *(float2*)(C + (size_t)row*N + col)     = o0;
                *(float2*)(C + (size_t)(row+8)*N + col) = o1;
            } else if (mode == 1){
                __half2 p0 = __floats2half2_rn(o0.x, o0.y);
                __half2 p1 = __floats2half2_rn(o1.x, o1.y);
                *(__half2*)(Ch + (size_t)row*N + col)     = p0;
                *(__half2*)(Ch + (size_t)(row+8)*N + col) = p1;
            } else {
                store_hl_h(Ch, (size_t)row*N + col, o0);
                store_hl_h(Ch, (size_t)(row+8)*N + col, o1);
            }
        }
    }
}

__global__ __launch_bounds__(256, 2)
void gemm_qkv(const __half* __restrict__ QI, const __half* __restrict__ KI,
              const __half* __restrict__ VI,
              const __half* __restrict__ WQ, const __half* __restrict__ WK,
              const __half* __restrict__ WV,
              const float* __restrict__ bq, const float* __restrict__ bk,
              const float* __restrict__ bv,
              __half* __restrict__ Q1, __half* __restrict__ K2, float* __restrict__ V)
{
    const int z = blockIdx.z;
    const __half* A  = (z == 0) ? QI : (z == 1) ? KI : VI;
    const __half* W  = (z == 0) ? WQ : (z == 1) ? WK : WV;
    const float* bias = (z == 0) ? bq : (z == 1) ? bk : bv;
    __half* Ch = (z == 0) ? Q1 : K2;
    int mode = (z == 0) ? 1 : (z == 1) ? 2 : 0;
    gemm_body(A, W, bias, V, Ch, mode);
}

__global__ __launch_bounds__(256, 2)
void gemm_out(const __half* __restrict__ A, const __half* __restrict__ W,
              const float* __restrict__ bias, float* __restrict__ C)
{
    gemm_body(A, W, bias, C, nullptr, 0);
}

// ============================================================
// scores: fp16 2-pass (Q single plane, K hi/lo), ldmatrix frags
// dyn smem: 3 x SCPLANE x 4B = 61440
// ============================================================
__global__ __launch_bounds__(256, 2)
void scores_mma(const __half* __restrict__ Q1, const __half* __restrict__ K2,
                const int* __restrict__ mask, float* __restrict__ attn)
{
    extern __shared__ __align__(16) uint32_t smw[];
    const uint32_t sb = (uint32_t)__cvta_generic_to_shared(smw);
    uint32_t* sQ  = smw;
    uint32_t* sKh = smw + SCPLANE;
    uint32_t* sKl = smw + 2*SCPLANE;

    const int tid = threadIdx.x, wid = tid >> 5, lane = tid & 31;
    const int wm = (wid >> 2)*64, wn = (wid & 3)*32;
    const int bh = blockIdx.z, b = bh >> 4, h = bh & 15;
    const int bm = blockIdx.y*128, bn = blockIdx.x*128;

#pragma unroll
    for (int i = 0; i < 4; i++){
        int u = tid + i*256;
        int ch = u >> 9, row = (u >> 2) & 127, s = u & 3;
        size_t gq = ((size_t)(b*SEQ + bm + row))*EMB + h*DH + ch*32 + s*8;
        size_t gk = ((size_t)(b*SEQ + bn + row))*EMB + h*DH + ch*32 + s*8;
        int wb = ch*GPLANE + row*SKW + s*4;
        *(uint4*)(sQ  + wb) = *(const uint4*)(Q1 + gq);
        *(uint4*)(sKh + wb) = *(const uint4*)(K2 + gk);
        *(uint4*)(sKl + wb) = *(const uint4*)(K2 + ACT + gk);
    }
    __syncthreads();

    float acc[4][4][4];
#pragma unroll
    for (int i = 0; i < 4; i++)
#pragma unroll
        for (int j = 0; j < 4; j++)
#pragma unroll
            for (int k = 0; k < 4; k++) acc[i][j][k] = 0.f;

    const uint32_t lo = ldsm_laneoff(lane);
    const uint32_t aOff  = (uint32_t)(wm*SKW*4) + lo;
    const uint32_t bOff  = (uint32_t)(wn*SKW*4) + lo;

#pragma unroll
    for (int ch = 0; ch < 2; ch++){
        uint32_t cb = sb + (uint32_t)(ch*GPLANE*4);
        mma_lds_h2<4,4>(acc, cb + aOff,
                        cb + (uint32_t)(SCPLANE*4) + bOff,
                        cb + (uint32_t)(2*SCPLANE*4) + bOff);
    }

    const int r = lane >> 2, cl = (lane & 3)*2;
    float* out = attn + (size_t)bh*SS;
#pragma unroll
    for (int mi = 0; mi < 4; mi++){
#pragma unroll
        for (int ni = 0; ni < 4; ni++){
            int row = bm + wm + mi*16 + r;
            int col = bn + wn + ni*8 + cl;
#pragma unroll
            for (int half = 0; half < 2; half++){
                int q = row + half*8;
                int2 m = *(const int2*)(mask + ((size_t)b*SEQ + q)*SEQ + col);
                float2 o;
                o.x = (m.x == 0) ? -1e9f : acc[mi][ni][half*2+0]*0.125f;
                o.y = (m.y == 0) ? -1e9f : acc[mi][ni][half*2+1]*0.125f;
                *(float2*)(out + (size_t)q*SEQ + col) = o;
            }
        }
    }
}

// ============================================================
// probs + head-average, coalesced (unchanged from R13)
// ============================================================
#define PSTR 1032
#define SM_STAT (16*PSTR*4)

__global__ __launch_bounds__(512)
void probs_avg(const float* __restrict__ attn, float* __restrict__ avg,
               __half* __restrict__ probs)
{
    extern __shared__ float sp[];
    const int bq = blockIdx.x, b = bq >> 10, q = bq & 1023;
    const int t = threadIdx.x, h = t >> 5, lane = t & 31;
    const float* row = attn + ((size_t)(b*NH + h)*SEQ + q)*SEQ;

    float4 v[8];
    float m = -3.0e38f;
#pragma unroll
    for (int i = 0; i < 8; i++){
        v[i] = ((const float4*)row)[i*32 + lane];
        m = fmaxf(m, fmaxf(fmaxf(v[i].x, v[i].y), fmaxf(v[i].z, v[i].w)));
    }
#pragma unroll
    for (int o = 16; o; o >>= 1) m = fmaxf(m, __shfl_xor_sync(0xffffffffu, m, o));

    float ssum = 0.f;
#pragma unroll
    for (int i = 0; i < 8; i++){
        v[i].x = __expf(v[i].x - m); v[i].y = __expf(v[i].y - m);
        v[i].z = __expf(v[i].z - m); v[i].w = __expf(v[i].w - m);
        ssum += v[i].x + v[i].y + v[i].z + v[i].w;
    }
#pragma unroll
    for (int o = 16; o; o >>= 1) ssum += __shfl_xor_sync(0xffffffffu, ssum, o);

    const float inv = 1.0f / ssum;
    __half* prow = probs + ((size_t)(b*NH + h)*SEQ + q)*SEQ;
    float* srow = sp + h*PSTR;
#pragma unroll
    for (int i = 0; i < 8; i++){
        v[i].x *= inv; v[i].y *= inv; v[i].z *= inv; v[i].w *= inv;
        __half2 p01 = __floats2half2_rn(v[i].x, v[i].y);
        __half2 p23 = __floats2half2_rn(v[i].z, v[i].w);
        uint2 u; u.x = *(uint32_t*)&p01; u.y = *(uint32_t*)&p23;
        *(uint2*)(prow + i*128 + lane*4) = u;
        *(float4*)(srow + i*128 + lane*4) = v[i];
    }
    __syncthreads();

    float2 a2 = make_float2(0.f, 0.f);
#pragma unroll
    for (int hh = 0; hh < 16; hh++){
        float2 p = *(const float2*)(sp + hh*PSTR + t*2);
        a2.x += p.x; a2.y += p.y;
    }
    a2.x *= 0.0625f; a2.y *= 0.0625f;
    *(float2*)(avg + ((size_t)b*SEQ + q)*SEQ + t*2) = a2;
}

// ============================================================
// ctx = P(fp16) @ V(fp16 hi/lo) -> fp16 plane; 3-stage + ldmatrix
// dyn smem: 3 x CTX2BUF x 4B = 61440
// ============================================================
__global__ __launch_bounds__(256, 2)
void ctx_mma(const __half* __restrict__ P, const __half* __restrict__ Vt2,
             __half* __restrict__ Cx)
{
    extern __shared__ __align__(16) uint32_t smw[];
    const uint32_t sb = (uint32_t)__cvta_generic_to_shared(smw);
    const int tid = threadIdx.x, wid = tid >> 5, lane = tid & 31;
    const int wm = (wid >> 2)*64, wn2 = (wid & 3)*16;
    const int bh = blockIdx.y, b = bh >> 4, h = bh & 15;
    const int bm = blockIdx.x*128;

    const int ar = tid >> 2, as = tid & 3;
    const __half* pA0 = P + (size_t)bh*SS + (size_t)(bm + ar)*SEQ + as*8;
    const __half* pA1 = P + (size_t)bh*SS + (size_t)(bm + ar + 64)*SEQ + as*8;
    const __half* pBh = Vt2 + ((size_t)b*EMB + h*DH + ar)*SEQ + as*8;

    const uint32_t wA0 = (ar*SKW + as*4)*4;
    const uint32_t wA1 = ((ar+64)*SKW + as*4)*4;
    const uint32_t wB  = (ar*SKW + as*4)*4;

    float acc[4][2][4];
#pragma unroll
    for (int i = 0; i < 4; i++)
#pragma unroll
        for (int j = 0; j < 2; j++)
#pragma unroll
            for (int k = 0; k < 4; k++) acc[i][j][k] = 0.f;

    const uint32_t lo = ldsm_laneoff(lane);
    const uint32_t aOff  = (uint32_t)(wm*SKW*4) + lo;
    const uint32_t bhOff = (uint32_t)(GPLANE*4) + (uint32_t)(wn2*SKW*4) + lo;
    const uint32_t blOff = (uint32_t)((GPLANE + BPLN)*4) + (uint32_t)(wn2*SKW*4) + lo;

    auto issue = [&](int c){
        uint32_t bbuf = sb + (c % 3)*(CTX2BUF*4);
        size_t go = (size_t)c*32;
        cp16(bbuf + wA0, pA0 + go);
        cp16(bbuf + wA1, pA1 + go);
        cp16(bbuf + GPLANE*4 + wB, pBh + go);
        cp16(bbuf + (GPLANE + BPLN)*4 + wB, pBh + ACT + go);
        CP_COMMIT();
    };

    issue(0);
    issue(1);
    for (int c = 0; c < 32; c++){
        CP_WAIT1();
        __syncthreads();
        if (c + 2 < 32) issue(c + 2);
        uint32_t cb = sb + (c % 3)*(CTX2BUF*4);
        mma_lds_h2<4,2>(acc, cb + aOff, cb + bhOff, cb + blOff);
    }

    const int r = lane >> 2, cl = (lane & 3)*2;
#pragma unroll
    for (int mi = 0; mi < 4; mi++){
#pragma unroll
        for (int ni = 0; ni < 2; ni++){
            int row = bm + wm + mi*16 + r;
            int col = h*DH + wn2 + ni*8 + cl;
            __half2 h0 = __floats2half2_rn(acc[mi][ni][0], acc[mi][ni][1]);
            __half2 h1 = __floats2half2_rn(acc[mi][ni][2], acc[mi][ni][3]);
            *(__half2*)(Cx + ((size_t)b*SEQ + row)*EMB + col)     = h0;
            *(__half2*)(Cx + ((size_t)b*SEQ + row + 8)*EMB + col) = h1;
        }
    }
}

// ============================================================
// V transpose + fp16 hi/lo split (unchanged)
// ============================================================
__global__ void transpose_k(const float* __restrict__ V, __half* __restrict__ Vt2)
{
    __shared__ float tile[32][33];
    const int b = blockIdx.z;
    const int e0 = blockIdx.x*32, s0 = blockIdx.y*32;
    const int tx = threadIdx.x, ty = threadIdx.y;
    const float* src = V + (size_t)b*SEQ*EMB;
#pragma unroll
    for (int i = 0; i < 32; i += 8)
        tile[ty + i][tx] = src[(size_t)(s0 + ty + i)*EMB + e0 + tx];
    __syncthreads();
#pragma unroll
    for (int i = 0; i < 32; i += 8){
        float v = tile[tx][ty + i];
        __half hb = __float2half_rn(v);
        size_t off = ((size_t)b*EMB + e0 + ty + i)*SEQ + s0 + tx;
        Vt2[off] = hb;
        Vt2[ACT + off] = __float2half_rn(v - __half2float(hb));
    }
}

// ============================================================
extern "C" void kernel_launch(void* const* d_in, const int* in_sizes, int n_in,
                              void* d_out, int out_size)
{
    const float* query = (const float*)d_in[0];
    const float* key   = (const float*)d_in[1];
    const float* value = (const float*)d_in[2];
    const int*   mask  = (const int*)  d_in[3];
    const float* Wq = (const float*)d_in[4];
    const float* bq = (const float*)d_in[5];
    const float* Wk = (const float*)d_in[6];
    const float* bk = (const float*)d_in[7];
    const float* Wv = (const float*)d_in[8];
    const float* bv = (const float*)d_in[9];
    const float* Wo = (const float*)d_in[10];
    const float* bo = (const float*)d_in[11];

    float* out      = (float*)d_out;
    float* attn_avg = out + ACT;

    float *V, *ATT; __half *PRB, *VT2;
    __half *QI, *KI, *VI, *WQ2, *WK2, *WV2, *WO2, *Q1, *K2;
    cudaGetSymbolAddress((void**)&V,   g_V);
    cudaGetSymbolAddress((void**)&ATT, g_attn);
    cudaGetSymbolAddress((void**)&PRB, g_probs);
    cudaGetSymbolAddress((void**)&QI,  g_qi);  cudaGetSymbolAddress((void**)&KI,  g_ki);
    cudaGetSymbolAddress((void**)&VI,  g_vi);
    cudaGetSymbolAddress((void**)&WQ2, g_Wq2); cudaGetSymbolAddress((void**)&WK2, g_Wk2);
    cudaGetSymbolAddress((void**)&WV2, g_Wv2); cudaGetSymbolAddress((void**)&WO2, g_Wo2);
    cudaGetSymbolAddress((void**)&Q1,  g_Q1);  cudaGetSymbolAddress((void**)&K2,  g_K2);
    cudaGetSymbolAddress((void**)&VT2, g_Vt2);
    __half* CTXH = Q1;   // ctx fp16 plane reuses Q1 (Q dead after scores)

    const int SM_GEMMD = 3*GBUF*4;       // 92160
    const int SM_SCOR  = 3*SCPLANE*4;    // 61440
    const int SM_CTX2  = 3*CTX2BUF*4;    // 61440

    cudaFuncSetAttribute(gemm_qkv,   cudaFuncAttributeMaxDynamicSharedMemorySize, SM_GEMMD);
    cudaFuncSetAttribute(gemm_out,   cudaFuncAttributeMaxDynamicSharedMemorySize, SM_GEMMD);
    cudaFuncSetAttribute(scores_mma, cudaFuncAttributeMaxDynamicSharedMemorySize, SM_SCOR);
    cudaFuncSetAttribute(ctx_mma,    cudaFuncAttributeMaxDynamicSharedMemorySize, SM_CTX2);
    cudaFuncSetAttribute(probs_avg,  cudaFuncAttributeMaxDynamicSharedMemorySize, SM_STAT);

    const int M = BATCH*SEQ;
    const int nact8 = (int)(ACT/8), nw8 = (int)(EE/8);

    split_act<<<dim3((nact8+255)/256, 3), 256>>>(query, key, value, QI, KI, VI, nact8);
    split_w  <<<dim3((nw8+255)/256, 4), 256>>>(Wq, Wk, Wv, Wo, WQ2, WK2, WV2, WO2, nw8);

    gemm_qkv<<<dim3(EMB/128, M/128, 3), 256, SM_GEMMD>>>(
        QI, KI, VI, WQ2, WK2, WV2, bq, bk, bv, Q1, K2, V);

    transpose_k<<<dim3(EMB/32, SEQ/32, BATCH), dim3(32, 8)>>>(V, VT2);

    scores_mma<<<dim3(SEQ/128, SEQ/128, BH), 256, SM_SCOR>>>(Q1, K2, mask, ATT);

    probs_avg<<<BATCH*SEQ, 512, SM_STAT>>>(ATT, attn_avg, PRB);

    ctx_mma<<<dim3(SEQ/128, BH), 256, SM_CTX2>>>(PRB, VT2, CTXH);

    gemm_out<<<dim3(EMB/128, M/128), 256, SM_GEMMD>>>(CTXH, WO2, bo, out);
}

// round 16
// speedup vs baseline: 1.0080x; 1.0080x over previous
#include <cuda_runtime.h>
#include <cuda_fp16.h>
#include <cstdint>
#include <cstddef>

#define SEQ 1024
#define EMB 1024
#define BATCH 4
#define NH 16
#define DH 64
#define BH (BATCH*NH)
#define SS ((size_t)SEQ*(size_t)SEQ)
#define ACT ((size_t)BATCH*SEQ*EMB)
#define EE  ((size_t)EMB*EMB)

#define SKW 20            // SMEM row stride (words): 16 data + 4 pad
#define GPLANE (128*SKW)  // one 128x32 16-bit plane (words)
#define BPLN   (64*SKW)
#define SCPLANE (2*GPLANE)
#define GBUF  (3*GPLANE)            // gemm stage: A + Wh + Wl
#define CTX2BUF (GPLANE + 2*BPLN)   // ctx stage: P + Vh + Vl

// ---- scratch ----
__device__ float g_attn[(size_t)BH*SEQ*SEQ];        // raw masked scores (fp32)
__device__ __half g_probs[(size_t)BH*SEQ*SEQ];      // normalized probs (fp16)
__device__ __half g_qi[ACT], g_ki[ACT], g_vi[ACT];  // fp16 activations
__device__ __half g_Wq2[2*EE], g_Wk2[2*EE], g_Wv2[2*EE], g_Wo2[2*EE];  // fp16 hi/lo
__device__ __half g_Q1[ACT];                        // Q fp16 single plane (reused for ctx)
__device__ __half g_K2[2*ACT];                      // K fp16 hi/lo
__device__ __half g_Vr2[2*ACT];                     // V fp16 hi/lo row-major
__device__ __half g_Vt2[2*ACT];                     // V^T fp16 hi/lo

// ============================================================
__device__ __forceinline__ void mma16816h(float* c, const uint32_t a[4], const uint32_t b[2]){
    asm volatile("mma.sync.aligned.m16n8k16.row.col.f32.f16.f16.f32 "
        "{%0,%1,%2,%3}, {%4,%5,%6,%7}, {%8,%9}, {%0,%1,%2,%3};"
        : "+f"(c[0]), "+f"(c[1]), "+f"(c[2]), "+f"(c[3])
        : "r"(a[0]), "r"(a[1]), "r"(a[2]), "r"(a[3]), "r"(b[0]), "r"(b[1]));
}

// fp16 hi/lo split of 8 floats
__device__ __forceinline__ void cvt8h(float4 x0, float4 x1, uint4& h, uint4& l){
    float x[8] = {x0.x,x0.y,x0.z,x0.w,x1.x,x1.y,x1.z,x1.w};
    __half hh[8], ll[8];
#pragma unroll
    for (int j = 0; j < 8; j++){
        hh[j] = __float2half_rn(x[j]);
        ll[j] = __float2half_rn(x[j] - __half2float(hh[j]));
    }
    h.x = (uint32_t)__half_as_ushort(hh[0]) | ((uint32_t)__half_as_ushort(hh[1])<<16);
    h.y = (uint32_t)__half_as_ushort(hh[2]) | ((uint32_t)__half_as_ushort(hh[3])<<16);
    h.z = (uint32_t)__half_as_ushort(hh[4]) | ((uint32_t)__half_as_ushort(hh[5])<<16);
    h.w = (uint32_t)__half_as_ushort(hh[6]) | ((uint32_t)__half_as_ushort(hh[7])<<16);
    l.x = (uint32_t)__half_as_ushort(ll[0]) | ((uint32_t)__half_as_ushort(ll[1])<<16);
    l.y = (uint32_t)__half_as_ushort(ll[2]) | ((uint32_t)__half_as_ushort(ll[3])<<16);
    l.z = (uint32_t)__half_as_ushort(ll[4]) | ((uint32_t)__half_as_ushort(ll[5])<<16);
    l.w = (uint32_t)__half_as_ushort(ll[6]) | ((uint32_t)__half_as_ushort(ll[7])<<16);
}

// fp16 2-pass chunk: single A plane, B hi/lo planes (R13 known-good)
template<int MT, int NT>
__device__ __forceinline__ void mma_chunk_h2(float acc[MT][NT][4],
    const uint32_t* __restrict__ sA,
    const uint32_t* __restrict__ sBh, const uint32_t* __restrict__ sBl,
    int mof, int nof, int lane)
{
    const int r = lane >> 2, w = lane & 3;
#pragma unroll
    for (int ks = 0; ks < 2; ks++){
        const int kw = ks*8 + w;
        uint32_t bh[NT][2], bl[NT][2];
#pragma unroll
        for (int ni = 0; ni < NT; ni++){
            int base = (nof + ni*8 + r)*SKW + kw;
            bh[ni][0] = sBh[base]; bh[ni][1] = sBh[base + 4];
            bl[ni][0] = sBl[base]; bl[ni][1] = sBl[base + 4];
        }
#pragma unroll
        for (int mi = 0; mi < MT; mi++){
            int base = (mof + mi*16 + r)*SKW + kw;
            uint32_t a[4];
            a[0] = sA[base];     a[1] = sA[base + 8*SKW];
            a[2] = sA[base + 4]; a[3] = sA[base + 8*SKW + 4];
#pragma unroll
            for (int ni = 0; ni < NT; ni++){
                mma16816h(acc[mi][ni], a, bh[ni]);
                mma16816h(acc[mi][ni], a, bl[ni]);
            }
        }
    }
}

__device__ __forceinline__ void store_hl_h(__half* H, size_t off, float2 v){
    __half hx = __float2half_rn(v.x), hy = __float2half_rn(v.y);
    __half2 hp; hp.x = hx; hp.y = hy;
    __half2 lp;
    lp.x = __float2half_rn(v.x - __half2float(hx));
    lp.y = __float2half_rn(v.y - __half2float(hy));
    *(__half2*)(H + off) = hp;
    *(__half2*)(H + ACT + off) = lp;
}

__device__ __forceinline__ void cp16(uint32_t dst, const void* src){
    asm volatile("cp.async.cg.shared.global [%0], [%1], 16;" :: "r"(dst), "l"(src));
}
#define CP_COMMIT() asm volatile("cp.async.commit_group;" ::: "memory")
#define CP_WAIT1()  asm volatile("cp.async.wait_group 1;" ::: "memory")

// ============================================================
// split kernels
// ============================================================
__global__ __launch_bounds__(256)
void split_act(const float* __restrict__ q, const float* __restrict__ k,
               const float* __restrict__ v,
               __half* __restrict__ qo, __half* __restrict__ ko, __half* __restrict__ vo,
               int n8)
{
    int i = blockIdx.x*blockDim.x + threadIdx.x;
    if (i >= n8) return;
    const float* src = (blockIdx.y == 0) ? q : (blockIdx.y == 1) ? k : v;
    __half* H = (blockIdx.y == 0) ? qo : (blockIdx.y == 1) ? ko : vo;
    const float* p = src + (size_t)i*8;
    float4 a = *(const float4*)p, b = *(const float4*)(p+4);
    __half2 h0 = __floats2half2_rn(a.x, a.y), h1 = __floats2half2_rn(a.z, a.w);
    __half2 h2 = __floats2half2_rn(b.x, b.y), h3 = __floats2half2_rn(b.z, b.w);
    uint4 u;
    u.x = *(uint32_t*)&h0; u.y = *(uint32_t*)&h1;
    u.z = *(uint32_t*)&h2; u.w = *(uint32_t*)&h3;
    *(uint4*)(H + (size_t)i*8) = u;
}

__global__ __launch_bounds__(256)
void split_w(const float* __restrict__ wq, const float* __restrict__ wk,
             const float* __restrict__ wv, const float* __restrict__ wo,
             __half* __restrict__ oq, __half* __restrict__ ok,
             __half* __restrict__ ov, __half* __restrict__ oo, int n8)
{
    int i = blockIdx.x*blockDim.x + threadIdx.x;
    if (i >= n8) return;
    const float* src = (blockIdx.y == 0) ? wq : (blockIdx.y == 1) ? wk :
                       (blockIdx.y == 2) ? wv : wo;
    __half* H = (blockIdx.y == 0) ? oq : (blockIdx.y == 1) ? ok :
                (blockIdx.y == 2) ? ov : oo;
    const float* p = src + (size_t)i*8;
    uint4 h, l;
    cvt8h(*(const float4*)p, *(const float4*)(p+4), h, l);
    *(uint4*)(H + (size_t)i*8) = h;
    *(uint4*)(H + EE + (size_t)i*8) = l;
}

// ============================================================
// GEMM body: fp16 2-pass (A single plane, W hi/lo), 3-stage cp.async.
// mode 0: fp32 C; mode 1: fp16 single plane Ch; mode 2: fp16 hi/lo Ch.
// bm/bn supplied by caller. dyn smem: 3 x GBUF x 4B = 92160
// ============================================================
__device__ __forceinline__ void gemm_body(
    const __half* __restrict__ A, const __half* __restrict__ W,
    const float* __restrict__ bias, float* __restrict__ C,
    __half* __restrict__ Ch, int mode, int bm, int bn)
{
    extern __shared__ __align__(16) uint32_t smw[];
    const uint32_t sb = (uint32_t)__cvta_generic_to_shared(smw);
    const int tid = threadIdx.x, wid = tid >> 5, lane = tid & 31;
    const int wm = (wid >> 2)*64, wn = (wid & 3)*32;
    const int r0 = tid >> 2, s0 = tid & 3;
    const int K = EMB, N = EMB;

    float acc[4][4][4];
#pragma unroll
    for (int i = 0; i < 4; i++)
#pragma unroll
        for (int j = 0; j < 4; j++)
#pragma unroll
            for (int k = 0; k < 4; k++) acc[i][j][k] = 0.f;

    const __half* pA0 = A + (size_t)(bm + r0)*K + s0*8;
    const __half* pA1 = A + (size_t)(bm + r0 + 64)*K + s0*8;
    const __half* pW0 = W + (size_t)(bn + r0)*K + s0*8;
    const __half* pW1 = W + (size_t)(bn + r0 + 64)*K + s0*8;

    const uint32_t w0 = (r0*SKW + s0*4)*4;
    const uint32_t w1 = ((r0+64)*SKW + s0*4)*4;

    auto issue = [&](int c){
        uint32_t b = sb + (c % 3)*(GBUF*4);
        size_t go = (size_t)c*32;
        cp16(b + 0*GPLANE*4 + w0, pA0 + go);
        cp16(b + 0*GPLANE*4 + w1, pA1 + go);
        cp16(b + 1*GPLANE*4 + w0, pW0 + go);
        cp16(b + 1*GPLANE*4 + w1, pW1 + go);
        cp16(b + 2*GPLANE*4 + w0, pW0 + EE + go);
        cp16(b + 2*GPLANE*4 + w1, pW1 + EE + go);
        CP_COMMIT();
    };

    const int nch = K >> 5;
    issue(0);
    issue(1);
    for (int c = 0; c < nch; c++){
        CP_WAIT1();
        __syncthreads();
        if (c + 2 < nch) issue(c + 2);
        uint32_t* cur = smw + (c % 3)*GBUF;
        mma_chunk_h2<4,4>(acc, cur, cur + GPLANE, cur + 2*GPLANE, wm, wn, lane);
    }

    const int r = lane >> 2, cl = (lane & 3)*2;
#pragma unroll
    for (int mi = 0; mi < 4; mi++){
#pragma unroll
        for (int ni = 0; ni < 4; ni++){
            int row = bm + wm + mi*16 + r;
            int col = bn + wn + ni*8 + cl;
            float2 bv = *(const float2*)(bias + col);
            float2 o0, o1;
            o0.x = acc[mi][ni][0] + bv.x; o0.y = acc[mi][ni][1] + bv.y;
            o1.x = acc[mi][ni][2] + bv.x; o1.y = acc[mi][ni][3] + bv.y;
            if (mode == 0){
                *(float2*)(C + (size_t)row*N + col)     = o0;
                *(float2*)(C + (size_t)(row+8)*N + col) = o1;
            } else if (mode == 1){
                __half2 p0 = __floats2half2_rn(o0.x, o0.y);
                __half2 p1 = __floats2half2_rn(o1.x, o1.y);
                *(__half2*)(Ch + (size_t)row*N + col)     = p0;
                *(__half2*)(Ch + (size_t)(row+8)*N + col) = p1;
            } else {
                store_hl_h(Ch, (size_t)row*N + col, o0);
                store_hl_h(Ch, (size_t)(row+8)*N + col, o1);
            }
        }
    }
}

// Q/K projections only (V moved into fused probs/V kernel)
__global__ __launch_bounds__(256, 2)
void gemm_qk(const __half* __restrict__ QI, const __half* __restrict__ KI,
             const __half* __restrict__ WQ, const __half* __restrict__ WK,
             const float* __restrict__ bq, const float* __restrict__ bk,
             __half* __restrict__ Q1, __half* __restrict__ K2)
{
    const int z = blockIdx.z;
    gemm_body((z == 0) ? QI : KI, (z == 0) ? WQ : WK,
              (z == 0) ? bq : bk, nullptr,
              (z == 0) ? Q1 : K2, (z == 0) ? 1 : 2,
              blockIdx.y*128, blockIdx.x*128);
}

__global__ __launch_bounds__(256, 2)
void gemm_out(const __half* __restrict__ A, const __half* __restrict__ W,
              const float* __restrict__ bias, float* __restrict__ C)
{
    gemm_body(A, W, bias, C, nullptr, 0, blockIdx.y*128, blockIdx.x*128);
}

// ============================================================
// scores: fp16 2-pass (Q single plane, K hi/lo), raw masked fp32 out
// dyn smem: 3 x SCPLANE x 4B = 61440
// ============================================================
__global__ __launch_bounds__(256, 2)
void scores_mma(const __half* __restrict__ Q1, const __half* __restrict__ K2,
                const int* __restrict__ mask, float* __restrict__ attn)
{
    extern __shared__ __align__(16) uint32_t smw[];
    uint32_t* sQ  = smw;
    uint32_t* sKh = smw + SCPLANE;
    uint32_t* sKl = smw + 2*SCPLANE;

    const int tid = threadIdx.x, wid = tid >> 5, lane = tid & 31;
    const int wm = (wid >> 2)*64, wn = (wid & 3)*32;
    const int bh = blockIdx.z, b = bh >> 4, h = bh & 15;
    const int bm = blockIdx.y*128, bn = blockIdx.x*128;

#pragma unroll
    for (int i = 0; i < 4; i++){
        int u = tid + i*256;
        int ch = u >> 9, row = (u >> 2) & 127, s = u & 3;
        size_t gq = ((size_t)(b*SEQ + bm + row))*EMB + h*DH + ch*32 + s*8;
        size_t gk = ((size_t)(b*SEQ + bn + row))*EMB + h*DH + ch*32 + s*8;
        int wb = ch*GPLANE + row*SKW + s*4;
        *(uint4*)(sQ  + wb) = *(const uint4*)(Q1 + gq);
        *(uint4*)(sKh + wb) = *(const uint4*)(K2 + gk);
        *(uint4*)(sKl + wb) = *(const uint4*)(K2 + ACT + gk);
    }
    __syncthreads();

    float acc[4][4][4];
#pragma unroll
    for (int i = 0; i < 4; i++)
#pragma unroll
        for (int j = 0; j < 4; j++)
#pragma unroll
            for (int k = 0; k < 4; k++) acc[i][j][k] = 0.f;

#pragma unroll
    for (int ch = 0; ch < 2; ch++)
        mma_chunk_h2<4,4>(acc, sQ + ch*GPLANE,
                          sKh + ch*GPLANE, sKl + ch*GPLANE, wm, wn, lane);

    const int r = lane >> 2, cl = (lane & 3)*2;
    float* out = attn + (size_t)bh*SS;
#pragma unroll
    for (int mi = 0; mi < 4; mi++){
#pragma unroll
        for (int ni = 0; ni < 4; ni++){
            int row = bm + wm + mi*16 + r;
            int col = bn + wn + ni*8 + cl;
#pragma unroll
            for (int half = 0; half < 2; half++){
                int q = row + half*8;
                int2 m = *(const int2*)(mask + ((size_t)b*SEQ + q)*SEQ + col);
                float2 o;
                o.x = (m.x == 0) ? -1e9f : acc[mi][ni][half*2+0]*0.125f;
                o.y = (m.y == 0) ? -1e9f : acc[mi][ni][half*2+1]*0.125f;
                *(float2*)(out + (size_t)q*SEQ + col) = o;
            }
        }
    }
}

// ============================================================
// FUSED probs_avg + V projection. 256 threads, 1D grid 256+4096.
//   bid <  256 : V GEMM tile (compute-bound, issued first)
//   bid >= 256 : probs row CTA (BW-bound, fills around V tiles)
// dyn smem: 92160 (gemm needs 3xGBUF; probs needs 66048)
// ============================================================
#define PSTR 1032
#define SM_FUSE (3*GBUF*4)   // 92160 >= 16*PSTR*4 = 66048

__global__ __launch_bounds__(256, 2)
void probs_vproj(const float* __restrict__ attn, float* __restrict__ avg,
                 __half* __restrict__ probs,
                 const __half* __restrict__ VI, const __half* __restrict__ WV,
                 const float* __restrict__ bv, __half* __restrict__ Vr2)
{
    extern __shared__ __align__(16) uint32_t smw[];
    const int bid = blockIdx.x;

    if (bid < 256){
        gemm_body(VI, WV, bv, nullptr, Vr2, 2, (bid >> 3)*128, (bid & 7)*128);
        return;
    }

    float* sp = (float*)smw;
    const int pid = bid - 256;
    const int b = pid >> 10, q = pid & 1023;
    const int t = threadIdx.x, w = t >> 5, lane = t & 31;

#pragma unroll 1
    for (int it = 0; it < 2; it++){
        const int h = w + it*8;
        const float* row = attn + ((size_t)(b*NH + h)*SEQ + q)*SEQ;

        float4 v[8];
        float m = -3.0e38f;
#pragma unroll
        for (int i = 0; i < 8; i++){
            v[i] = ((const float4*)row)[i*32 + lane];
            m = fmaxf(m, fmaxf(fmaxf(v[i].x, v[i].y), fmaxf(v[i].z, v[i].w)));
        }
#pragma unroll
        for (int o = 16; o; o >>= 1) m = fmaxf(m, __shfl_xor_sync(0xffffffffu, m, o));

        float ssum = 0.f;
#pragma unroll
        for (int i = 0; i < 8; i++){
            v[i].x = __expf(v[i].x - m); v[i].y = __expf(v[i].y - m);
            v[i].z = __expf(v[i].z - m); v[i].w = __expf(v[i].w - m);
            ssum += v[i].x + v[i].y + v[i].z + v[i].w;
        }
#pragma unroll
        for (int o = 16; o; o >>= 1) ssum += __shfl_xor_sync(0xffffffffu, ssum, o);

        const float inv = 1.0f / ssum;
        __half* prow = probs + ((size_t)(b*NH + h)*SEQ + q)*SEQ;
        float* srow = sp + h*PSTR;
#pragma unroll
        for (int i = 0; i < 8; i++){
            v[i].x *= inv; v[i].y *= inv; v[i].z *= inv; v[i].w *= inv;
            __half2 p01 = __floats2half2_rn(v[i].x, v[i].y);
            __half2 p23 = __floats2half2_rn(v[i].z, v[i].w);
            uint2 u; u.x = *(uint32_t*)&p01; u.y = *(uint32_t*)&p23;
            *(uint2*)(prow + i*128 + lane*4) = u;
            *(float4*)(srow + i*128 + lane*4) = v[i];
        }
    }
    __syncthreads();

    // cross-head average: thread t owns columns 4t..4t+3
    float4 a4 = make_float4(0.f, 0.f, 0.f, 0.f);
#pragma unroll
    for (int hh = 0; hh < 16; hh++){
        float4 p = *(const float4*)(sp + hh*PSTR + t*4);
        a4.x += p.x; a4.y += p.y; a4.z += p.z; a4.w += p.w;
    }
    a4.x *= 0.0625f; a4.y *= 0.0625f; a4.z *= 0.0625f; a4.w *= 0.0625f;
    *(float4*)(avg + ((size_t)b*SEQ + q)*SEQ + t*4) = a4;
}

// ============================================================
// ctx = P(fp16) @ V(fp16 hi/lo): 3-stage cp.async, 2-pass (R13)
// dyn smem: 3 x CTX2BUF x 4B = 61440
// ============================================================
__global__ __launch_bounds__(256, 2)
void ctx_mma(const __half* __restrict__ P, const __half* __restrict__ Vt2,
             __half* __restrict__ Cx)
{
    extern __shared__ __align__(16) uint32_t smw[];
    const uint32_t sb = (uint32_t)__cvta_generic_to_shared(smw);
    const int tid = threadIdx.x, wid = tid >> 5, lane = tid & 31;
    const int wm = (wid >> 2)*64, wn2 = (wid & 3)*16;
    const int bh = blockIdx.y, b = bh >> 4, h = bh & 15;
    const int bm = blockIdx.x*128;

    const int ar = tid >> 2, as = tid & 3;
    const __half* pA0 = P + (size_t)bh*SS + (size_t)(bm + ar)*SEQ + as*8;
    const __half* pA1 = P + (size_t)bh*SS + (size_t)(bm + ar + 64)*SEQ + as*8;
    const __half* pBh = Vt2 + ((size_t)b*EMB + h*DH + ar)*SEQ + as*8;

    const uint32_t wA0 = (ar*SKW + as*4)*4;
    const uint32_t wA1 = ((ar+64)*SKW + as*4)*4;
    const uint32_t wB  = (ar*SKW + as*4)*4;

    float acc[4][2][4];
#pragma unroll
    for (int i = 0; i < 4; i++)
#pragma unroll
        for (int j = 0; j < 2; j++)
#pragma unroll
            for (int k = 0; k < 4; k++) acc[i][j][k] = 0.f;

    auto issue = [&](int c){
        uint32_t bbuf = sb + (c % 3)*(CTX2BUF*4);
        size_t go = (size_t)c*32;
        cp16(bbuf + wA0, pA0 + go);
        cp16(bbuf + wA1, pA1 + go);
        cp16(bbuf + GPLANE*4 + wB, pBh + go);
        cp16(bbuf + (GPLANE + BPLN)*4 + wB, pBh + ACT + go);
        CP_COMMIT();
    };

    issue(0);
    issue(1);
    for (int c = 0; c < 32; c++){
        CP_WAIT1();
        __syncthreads();
        if (c + 2 < 32) issue(c + 2);
        uint32_t* cur = smw + (c % 3)*CTX2BUF;
        mma_chunk_h2<4,2>(acc, cur, cur + GPLANE, cur + GPLANE + BPLN, wm, wn2, lane);
    }

    const int r = lane >> 2, cl = (lane & 3)*2;
#pragma unroll
    for (int mi = 0; mi < 4; mi++){
#pragma unroll
        for (int ni = 0; ni < 2; ni++){
            int row = bm + wm + mi*16 + r;
            int col = h*DH + wn2 + ni*8 + cl;
            __half2 h0 = __floats2half2_rn(acc[mi][ni][0], acc[mi][ni][1]);
            __half2 h1 = __floats2half2_rn(acc[mi][ni][2], acc[mi][ni][3]);
            *(__half2*)(Cx + ((size_t)b*SEQ + row)*EMB + col)     = h0;
            *(__half2*)(Cx + ((size_t)b*SEQ + row + 8)*EMB + col) = h1;
        }
    }
}

// ============================================================
// V transpose fp16 -> fp16, both planes: z = plane*4 + b
// ============================================================
__global__ void transpose_k(const __half* __restrict__ Vr2, __half* __restrict__ Vt2)
{
    __shared__ __half tile[32][33];
    const int b = blockIdx.z & 3;
    const size_t pl = (size_t)(blockIdx.z >> 2)*ACT;
    const int e0 = blockIdx.x*32, s0 = blockIdx.y*32;
    const int tx = threadIdx.x, ty = threadIdx.y;
    const __half* src = Vr2 + pl + (size_t)b*SEQ*EMB;
#pragma unroll
    for (int i = 0; i < 32; i += 8)
        tile[ty + i][tx] = src[(size_t)(s0 + ty + i)*EMB + e0 + tx];
    __syncthreads();
#pragma unroll
    for (int i = 0; i < 32; i += 8)
        Vt2[pl + ((size_t)b*EMB + e0 + ty + i)*SEQ + s0 + tx] = tile[tx][ty + i];
}

// ============================================================
extern "C" void kernel_launch(void* const* d_in, const int* in_sizes, int n_in,
                              void* d_out, int out_size)
{
    const float* query = (const float*)d_in[0];
    const float* key   = (const float*)d_in[1];
    const float* value = (const float*)d_in[2];
    const int*   mask  = (const int*)  d_in[3];
    const float* Wq = (const float*)d_in[4];
    const float* bq = (const float*)d_in[5];
    const float* Wk = (const float*)d_in[6];
    const float* bk = (const float*)d_in[7];
    const float* Wv = (const float*)d_in[8];
    const float* bv = (const float*)d_in[9];
    const float* Wo = (const float*)d_in[10];
    const float* bo = (const float*)d_in[11];

    float* out      = (float*)d_out;
    float* attn_avg = out + ACT;

    float* ATT; __half *PRB, *VR2, *VT2;
    __half *QI, *KI, *VI, *WQ2, *WK2, *WV2, *WO2, *Q1, *K2;
    cudaGetSymbolAddress((void**)&ATT, g_attn);
    cudaGetSymbolAddress((void**)&PRB, g_probs);
    cudaGetSymbolAddress((void**)&QI,  g_qi);  cudaGetSymbolAddress((void**)&KI,  g_ki);
    cudaGetSymbolAddress((void**)&VI,  g_vi);
    cudaGetSymbolAddress((void**)&WQ2, g_Wq2); cudaGetSymbolAddress((void**)&WK2, g_Wk2);
    cudaGetSymbolAddress((void**)&WV2, g_Wv2); cudaGetSymbolAddress((void**)&WO2, g_Wo2);
    cudaGetSymbolAddress((void**)&Q1,  g_Q1);  cudaGetSymbolAddress((void**)&K2,  g_K2);
    cudaGetSymbolAddress((void**)&VR2, g_Vr2); cudaGetSymbolAddress((void**)&VT2, g_Vt2);
    __half* CTXH = Q1;   // ctx fp16 plane reuses Q1 (Q dead after scores)

    const int SM_GEMMD = 3*GBUF*4;       // 92160
    const int SM_SCOR  = 3*SCPLANE*4;    // 61440
    const int SM_CTX2  = 3*CTX2BUF*4;    // 61440

    cudaFuncSetAttribute(gemm_qk,    cudaFuncAttributeMaxDynamicSharedMemorySize, SM_GEMMD);
    cudaFuncSetAttribute(gemm_out,   cudaFuncAttributeMaxDynamicSharedMemorySize, SM_GEMMD);
    cudaFuncSetAttribute(scores_mma, cudaFuncAttributeMaxDynamicSharedMemorySize, SM_SCOR);
    cudaFuncSetAttribute(ctx_mma,    cudaFuncAttributeMaxDynamicSharedMemorySize, SM_CTX2);
    cudaFuncSetAttribute(probs_vproj,cudaFuncAttributeMaxDynamicSharedMemorySize, SM_FUSE);

    const int M = BATCH*SEQ;
    const int nact8 = (int)(ACT/8), nw8 = (int)(EE/8);

    split_act<<<dim3((nact8+255)/256, 3), 256>>>(query, key, value, QI, KI, VI, nact8);
    split_w  <<<dim3((nw8+255)/256, 4), 256>>>(Wq, Wk, Wv, Wo, WQ2, WK2, WV2, WO2, nw8);

    gemm_qk<<<dim3(EMB/128, M/128, 2), 256, SM_GEMMD>>>(QI, KI, WQ2, WK2, bq, bk, Q1, K2);

    scores_mma<<<dim3(SEQ/128, SEQ/128, BH), 256, SM_SCOR>>>(Q1, K2, mask, ATT);

    // fused: V projection (256 CTAs) + probs/avg (4096 CTAs)
    probs_vproj<<<256 + BATCH*SEQ, 256, SM_FUSE>>>(ATT, attn_avg, PRB, VI, WV2, bv, VR2);

    transpose_k<<<dim3(EMB/32, SEQ/32, 2*BATCH), dim3(32, 8)>>>(VR2, VT2);

    ctx_mma<<<dim3(SEQ/128, BH), 256, SM_CTX2>>>(PRB, VT2, CTXH);

    gemm_out<<<dim3(EMB/128, M/128), 256, SM_GEMMD>>>(CTXH, WO2, bo, out);
}

// round 17
// speedup vs baseline: 1.0404x; 1.0322x over previous
#include <cuda_runtime.h>
#include <cuda_fp16.h>
#include <cstdint>
#include <cstddef>

#define SEQ 1024
#define EMB 1024
#define BATCH 4
#define NH 16
#define DH 64
#define BH (BATCH*NH)
#define SS ((size_t)SEQ*(size_t)SEQ)
#define ACT ((size_t)BATCH*SEQ*EMB)
#define EE  ((size_t)EMB*EMB)

#define SKW 20            // SMEM row stride (words): 16 data + 4 pad
#define GPLANE (128*SKW)  // one 128x32 16-bit plane (words)
#define BPLN   (64*SKW)
#define SCPLANE (2*GPLANE)
#define GBUF  (3*GPLANE)            // gemm stage: A + Wh + Wl
#define CTX2BUF (GPLANE + 2*BPLN)   // ctx stage: P + Vh + Vl
#define STSTR 132                   // scores staging row stride (floats)

// ---- scratch ----
__device__ float g_attn[(size_t)BH*SEQ*SEQ];        // raw masked scores (fp32)
__device__ __half g_probs[(size_t)BH*SEQ*SEQ];      // normalized probs (fp16)
__device__ __half g_qi[ACT], g_ki[ACT], g_vi[ACT];  // fp16 activations
__device__ __half g_Wq2[2*EE], g_Wk2[2*EE], g_Wv2[2*EE], g_Wo2[2*EE];  // fp16 hi/lo
__device__ __half g_Q1[ACT];                        // Q fp16 single plane (reused for ctx)
__device__ __half g_K2[2*ACT];                      // K fp16 hi/lo
__device__ __half g_Vr2[2*ACT];                     // V fp16 hi/lo row-major
__device__ __half g_Vt2[2*ACT];                     // V^T fp16 hi/lo

// ============================================================
__device__ __forceinline__ void mma16816h(float* c, const uint32_t a[4], const uint32_t b[2]){
    asm volatile("mma.sync.aligned.m16n8k16.row.col.f32.f16.f16.f32 "
        "{%0,%1,%2,%3}, {%4,%5,%6,%7}, {%8,%9}, {%0,%1,%2,%3};"
        : "+f"(c[0]), "+f"(c[1]), "+f"(c[2]), "+f"(c[3])
        : "r"(a[0]), "r"(a[1]), "r"(a[2]), "r"(a[3]), "r"(b[0]), "r"(b[1]));
}

// fp16 hi/lo split of 8 floats
__device__ __forceinline__ void cvt8h(float4 x0, float4 x1, uint4& h, uint4& l){
    float x[8] = {x0.x,x0.y,x0.z,x0.w,x1.x,x1.y,x1.z,x1.w};
    __half hh[8], ll[8];
#pragma unroll
    for (int j = 0; j < 8; j++){
        hh[j] = __float2half_rn(x[j]);
        ll[j] = __float2half_rn(x[j] - __half2float(hh[j]));
    }
    h.x = (uint32_t)__half_as_ushort(hh[0]) | ((uint32_t)__half_as_ushort(hh[1])<<16);
    h.y = (uint32_t)__half_as_ushort(hh[2]) | ((uint32_t)__half_as_ushort(hh[3])<<16);
    h.z = (uint32_t)__half_as_ushort(hh[4]) | ((uint32_t)__half_as_ushort(hh[5])<<16);
    h.w = (uint32_t)__half_as_ushort(hh[6]) | ((uint32_t)__half_as_ushort(hh[7])<<16);
    l.x = (uint32_t)__half_as_ushort(ll[0]) | ((uint32_t)__half_as_ushort(ll[1])<<16);
    l.y = (uint32_t)__half_as_ushort(ll[2]) | ((uint32_t)__half_as_ushort(ll[3])<<16);
    l.z = (uint32_t)__half_as_ushort(ll[4]) | ((uint32_t)__half_as_ushort(ll[5])<<16);
    l.w = (uint32_t)__half_as_ushort(ll[6]) | ((uint32_t)__half_as_ushort(ll[7])<<16);
}

// fp16 2-pass chunk: single A plane, B hi/lo planes (R13 known-good)
template<int MT, int NT>
__device__ __forceinline__ void mma_chunk_h2(float acc[MT][NT][4],
    const uint32_t* __restrict__ sA,
    const uint32_t* __restrict__ sBh, const uint32_t* __restrict__ sBl,
    int mof, int nof, int lane)
{
    const int r = lane >> 2, w = lane & 3;
#pragma unroll
    for (int ks = 0; ks < 2; ks++){
        const int kw = ks*8 + w;
        uint32_t bh[NT][2], bl[NT][2];
#pragma unroll
        for (int ni = 0; ni < NT; ni++){
            int base = (nof + ni*8 + r)*SKW + kw;
            bh[ni][0] = sBh[base]; bh[ni][1] = sBh[base + 4];
            bl[ni][0] = sBl[base]; bl[ni][1] = sBl[base + 4];
        }
#pragma unroll
        for (int mi = 0; mi < MT; mi++){
            int base = (mof + mi*16 + r)*SKW + kw;
            uint32_t a[4];
            a[0] = sA[base];     a[1] = sA[base + 8*SKW];
            a[2] = sA[base + 4]; a[3] = sA[base + 8*SKW + 4];
#pragma unroll
            for (int ni = 0; ni < NT; ni++){
                mma16816h(acc[mi][ni], a, bh[ni]);
                mma16816h(acc[mi][ni], a, bl[ni]);
            }
        }
    }
}

__device__ __forceinline__ void store_hl_h(__half* H, size_t off, float2 v){
    __half hx = __float2half_rn(v.x), hy = __float2half_rn(v.y);
    __half2 hp; hp.x = hx; hp.y = hy;
    __half2 lp;
    lp.x = __float2half_rn(v.x - __half2float(hx));
    lp.y = __float2half_rn(v.y - __half2float(hy));
    *(__half2*)(H + off) = hp;
    *(__half2*)(H + ACT + off) = lp;
}

__device__ __forceinline__ void cp16(uint32_t dst, const void* src){
    asm volatile("cp.async.cg.shared.global [%0], [%1], 16;" :: "r"(dst), "l"(src));
}
#define CP_COMMIT() asm volatile("cp.async.commit_group;" ::: "memory")
#define CP_WAIT0()  asm volatile("cp.async.wait_group 0;" ::: "memory")
#define CP_WAIT1()  asm volatile("cp.async.wait_group 1;" ::: "memory")

// ============================================================
// split kernels
// ============================================================
__global__ __launch_bounds__(256)
void split_act(const float* __restrict__ q, const float* __restrict__ k,
               const float* __restrict__ v,
               __half* __restrict__ qo, __half* __restrict__ ko, __half* __restrict__ vo,
               int n8)
{
    int i = blockIdx.x*blockDim.x + threadIdx.x;
    if (i >= n8) return;
    const float* src = (blockIdx.y == 0) ? q : (blockIdx.y == 1) ? k : v;
    __half* H = (blockIdx.y == 0) ? qo : (blockIdx.y == 1) ? ko : vo;
    const float* p = src + (size_t)i*8;
    float4 a = *(const float4*)p, b = *(const float4*)(p+4);
    __half2 h0 = __floats2half2_rn(a.x, a.y), h1 = __floats2half2_rn(a.z, a.w);
    __half2 h2 = __floats2half2_rn(b.x, b.y), h3 = __floats2half2_rn(b.z, b.w);
    uint4 u;
    u.x = *(uint32_t*)&h0; u.y = *(uint32_t*)&h1;
    u.z = *(uint32_t*)&h2; u.w = *(uint32_t*)&h3;
    *(uint4*)(H + (size_t)i*8) = u;
}

__global__ __launch_bounds__(256)
void split_w(const float* __restrict__ wq, const float* __restrict__ wk,
             const float* __restrict__ wv, const float* __restrict__ wo,
             __half* __restrict__ oq, __half* __restrict__ ok,
             __half* __restrict__ ov, __half* __restrict__ oo, int n8)
{
    int i = blockIdx.x*blockDim.x + threadIdx.x;
    if (i >= n8) return;
    const float* src = (blockIdx.y == 0) ? wq : (blockIdx.y == 1) ? wk :
                       (blockIdx.y == 2) ? wv : wo;
    __half* H = (blockIdx.y == 0) ? oq : (blockIdx.y == 1) ? ok :
                (blockIdx.y == 2) ? ov : oo;
    const float* p = src + (size_t)i*8;
    uint4 h, l;
    cvt8h(*(const float4*)p, *(const float4*)(p+4), h, l);
    *(uint4*)(H + (size_t)i*8) = h;
    *(uint4*)(H + EE + (size_t)i*8) = l;
}

// ============================================================
// GEMM body: fp16 2-pass (A single plane, W hi/lo), 3-stage cp.async.
// mode 0: fp32 C; mode 1: fp16 single plane Ch; mode 2: fp16 hi/lo Ch.
// ============================================================
__device__ __forceinline__ void gemm_body(
    const __half* __restrict__ A, const __half* __restrict__ W,
    const float* __restrict__ bias, float* __restrict__ C,
    __half* __restrict__ Ch, int mode, int bm, int bn)
{
    extern __shared__ __align__(16) uint32_t smw[];
    const uint32_t sb = (uint32_t)__cvta_generic_to_shared(smw);
    const int tid = threadIdx.x, wid = tid >> 5, lane = tid & 31;
    const int wm = (wid >> 2)*64, wn = (wid & 3)*32;
    const int r0 = tid >> 2, s0 = tid & 3;
    const int K = EMB, N = EMB;

    float acc[4][4][4];
#pragma unroll
    for (int i = 0; i < 4; i++)
#pragma unroll
        for (int j = 0; j < 4; j++)
#pragma unroll
            for (int k = 0; k < 4; k++) acc[i][j][k] = 0.f;

    const __half* pA0 = A + (size_t)(bm + r0)*K + s0*8;
    const __half* pA1 = A + (size_t)(bm + r0 + 64)*K + s0*8;
    const __half* pW0 = W + (size_t)(bn + r0)*K + s0*8;
    const __half* pW1 = W + (size_t)(bn + r0 + 64)*K + s0*8;

    const uint32_t w0 = (r0*SKW + s0*4)*4;
    const uint32_t w1 = ((r0+64)*SKW + s0*4)*4;

    auto issue = [&](int c){
        uint32_t b = sb + (c % 3)*(GBUF*4);
        size_t go = (size_t)c*32;
        cp16(b + 0*GPLANE*4 + w0, pA0 + go);
        cp16(b + 0*GPLANE*4 + w1, pA1 + go);
        cp16(b + 1*GPLANE*4 + w0, pW0 + go);
        cp16(b + 1*GPLANE*4 + w1, pW1 + go);
        cp16(b + 2*GPLANE*4 + w0, pW0 + EE + go);
        cp16(b + 2*GPLANE*4 + w1, pW1 + EE + go);
        CP_COMMIT();
    };

    const int nch = K >> 5;
    issue(0);
    issue(1);
    for (int c = 0; c < nch; c++){
        CP_WAIT1();
        __syncthreads();
        if (c + 2 < nch) issue(c + 2);
        uint32_t* cur = smw + (c % 3)*GBUF;
        mma_chunk_h2<4,4>(acc, cur, cur + GPLANE, cur + 2*GPLANE, wm, wn, lane);
    }

    const int r = lane >> 2, cl = (lane & 3)*2;
#pragma unroll
    for (int mi = 0; mi < 4; mi++){
#pragma unroll
        for (int ni = 0; ni < 4; ni++){
            int row = bm + wm + mi*16 + r;
            int col = bn + wn + ni*8 + cl;
            float2 bv = *(const float2*)(bias + col);
            float2 o0, o1;
            o0.x = acc[mi][ni][0] + bv.x; o0.y = acc[mi][ni][1] + bv.y;
            o1.x = acc[mi][ni][2] + bv.x; o1.y = acc[mi][ni][3] + bv.y;
            if (mode == 0){
                *(float2*)(C + (size_t)row*N + col)     = o0;
                *(float2*)(C + (size_t)(row+8)*N + col) = o1;
            } else if (mode == 1){
                __half2 p0 = __floats2half2_rn(o0.x, o0.y);
                __half2 p1 = __floats2half2_rn(o1.x, o1.y);
                *(__half2*)(Ch + (size_t)row*N + col)     = p0;
                *(__half2*)(Ch + (size_t)(row+8)*N + col) = p1;
            } else {
                store_hl_h(Ch, (size_t)row*N + col, o0);
                store_hl_h(Ch, (size_t)(row+8)*N + col, o1);
            }
        }
    }
}

__global__ __launch_bounds__(256, 2)
void gemm_qk(const __half* __restrict__ QI, const __half* __restrict__ KI,
             const __half* __restrict__ WQ, const __half* __restrict__ WK,
             const float* __restrict__ bq, const float* __restrict__ bk,
             __half* __restrict__ Q1, __half* __restrict__ K2)
{
    const int z = blockIdx.z;
    gemm_body((z == 0) ? QI : KI, (z == 0) ? WQ : WK,
              (z == 0) ? bq : bk, nullptr,
              (z == 0) ? Q1 : K2, (z == 0) ? 1 : 2,
              blockIdx.y*128, blockIdx.x*128);
}

__global__ __launch_bounds__(256, 2)
void gemm_out(const __half* __restrict__ A, const __half* __restrict__ W,
              const float* __restrict__ bias, float* __restrict__ C)
{
    gemm_body(A, W, bias, C, nullptr, 0, blockIdx.y*128, blockIdx.x*128);
}

// ============================================================
// scores v2: cp.async tile loads + SMEM-staged coalesced epilogue.
// dyn smem: max(tiles 61440, staging 128*132*4=67584) = 67584
// ============================================================
#define SM_SCOR (128*STSTR*4)   // 67584

__global__ __launch_bounds__(256, 2)
void scores_mma(const __half* __restrict__ Q1, const __half* __restrict__ K2,
                const int* __restrict__ mask, float* __restrict__ attn)
{
    extern __shared__ __align__(16) uint32_t smw[];
    const uint32_t sb = (uint32_t)__cvta_generic_to_shared(smw);
    uint32_t* sQ  = smw;
    uint32_t* sKh = smw + SCPLANE;
    uint32_t* sKl = smw + 2*SCPLANE;

    const int tid = threadIdx.x, wid = tid >> 5, lane = tid & 31;
    const int wm = (wid >> 2)*64, wn = (wid & 3)*32;
    const int bh = blockIdx.z, b = bh >> 4, h = bh & 15;
    const int bm = blockIdx.y*128, bn = blockIdx.x*128;

    // cp.async tile loads: 12 x 16B per thread
#pragma unroll
    for (int i = 0; i < 4; i++){
        int u = tid + i*256;
        int ch = u >> 9, row = (u >> 2) & 127, s = u & 3;
        size_t gq = ((size_t)(b*SEQ + bm + row))*EMB + h*DH + ch*32 + s*8;
        size_t gk = ((size_t)(b*SEQ + bn + row))*EMB + h*DH + ch*32 + s*8;
        uint32_t wb = (uint32_t)(ch*GPLANE + row*SKW + s*4)*4;
        cp16(sb + wb, Q1 + gq);
        cp16(sb + SCPLANE*4 + wb, K2 + gk);
        cp16(sb + 2*SCPLANE*4 + wb, K2 + ACT + gk);
    }
    CP_COMMIT();
    CP_WAIT0();
    __syncthreads();

    float acc[4][4][4];
#pragma unroll
    for (int i = 0; i < 4; i++)
#pragma unroll
        for (int j = 0; j < 4; j++)
#pragma unroll
            for (int k = 0; k < 4; k++) acc[i][j][k] = 0.f;

#pragma unroll
    for (int ch = 0; ch < 2; ch++)
        mma_chunk_h2<4,4>(acc, sQ + ch*GPLANE,
                          sKh + ch*GPLANE, sKl + ch*GPLANE, wm, wn, lane);

    // ---- staged coalesced epilogue ----
    __syncthreads();                      // tiles no longer needed
    float* st = (float*)smw;
    const int r = lane >> 2, cl = (lane & 3)*2;
#pragma unroll
    for (int mi = 0; mi < 4; mi++){
#pragma unroll
        for (int ni = 0; ni < 4; ni++){
            int col = wn + ni*8 + cl;
#pragma unroll
            for (int half = 0; half < 2; half++){
                int row = wm + mi*16 + r + half*8;
                float2 o;
                o.x = acc[mi][ni][half*2+0]*0.125f;
                o.y = acc[mi][ni][half*2+1]*0.125f;
                *(float2*)(st + row*STSTR + col) = o;
            }
        }
    }
    __syncthreads();

    float* out = attn + (size_t)bh*SS;
#pragma unroll
    for (int i = 0; i < 16; i++){
        int idx = tid + i*256;
        int row = idx >> 5, seg = idx & 31;
        float4 v = *(const float4*)(st + row*STSTR + seg*4);
        const int* mrow = mask + ((size_t)(b*SEQ + bm + row))*SEQ + bn + seg*4;
        int4 m = *(const int4*)mrow;
        v.x = (m.x == 0) ? -1e9f : v.x;
        v.y = (m.y == 0) ? -1e9f : v.y;
        v.z = (m.z == 0) ? -1e9f : v.z;
        v.w = (m.w == 0) ? -1e9f : v.w;
        *(float4*)(out + (size_t)(bm + row)*SEQ + bn + seg*4) = v;
    }
}

// ============================================================
// FUSED probs_avg + V projection (R16 known-good)
// ============================================================
#define PSTR 1032
#define SM_FUSE (3*GBUF*4)   // 92160 >= 16*PSTR*4 = 66048

__global__ __launch_bounds__(256, 2)
void probs_vproj(const float* __restrict__ attn, float* __restrict__ avg,
                 __half* __restrict__ probs,
                 const __half* __restrict__ VI, const __half* __restrict__ WV,
                 const float* __restrict__ bv, __half* __restrict__ Vr2)
{
    extern __shared__ __align__(16) uint32_t smw[];
    const int bid = blockIdx.x;

    if (bid < 256){
        gemm_body(VI, WV, bv, nullptr, Vr2, 2, (bid >> 3)*128, (bid & 7)*128);
        return;
    }

    float* sp = (float*)smw;
    const int pid = bid - 256;
    const int b = pid >> 10, q = pid & 1023;
    const int t = threadIdx.x, w = t >> 5, lane = t & 31;

#pragma unroll 1
    for (int it = 0; it < 2; it++){
        const int h = w + it*8;
        const float* row = attn + ((size_t)(b*NH + h)*SEQ + q)*SEQ;

        float4 v[8];
        float m = -3.0e38f;
#pragma unroll
        for (int i = 0; i < 8; i++){
            v[i] = ((const float4*)row)[i*32 + lane];
            m = fmaxf(m, fmaxf(fmaxf(v[i].x, v[i].y), fmaxf(v[i].z, v[i].w)));
        }
#pragma unroll
        for (int o = 16; o; o >>= 1) m = fmaxf(m, __shfl_xor_sync(0xffffffffu, m, o));

        float ssum = 0.f;
#pragma unroll
        for (int i = 0; i < 8; i++){
            v[i].x = __expf(v[i].x - m); v[i].y = __expf(v[i].y - m);
            v[i].z = __expf(v[i].z - m); v[i].w = __expf(v[i].w - m);
            ssum += v[i].x + v[i].y + v[i].z + v[i].w;
        }
#pragma unroll
        for (int o = 16; o; o >>= 1) ssum += __shfl_xor_sync(0xffffffffu, ssum, o);

        const float inv = 1.0f / ssum;
        __half* prow = probs + ((size_t)(b*NH + h)*SEQ + q)*SEQ;
        float* srow = sp + h*PSTR;
#pragma unroll
        for (int i = 0; i < 8; i++){
            v[i].x *= inv; v[i].y *= inv; v[i].z *= inv; v[i].w *= inv;
            __half2 p01 = __floats2half2_rn(v[i].x, v[i].y);
            __half2 p23 = __floats2half2_rn(v[i].z, v[i].w);
            uint2 u; u.x = *(uint32_t*)&p01; u.y = *(uint32_t*)&p23;
            *(uint2*)(prow + i*128 + lane*4) = u;
            *(float4*)(srow + i*128 + lane*4) = v[i];
        }
    }
    __syncthreads();

    float4 a4 = make_float4(0.f, 0.f, 0.f, 0.f);
#pragma unroll
    for (int hh = 0; hh < 16; hh++){
        float4 p = *(const float4*)(sp + hh*PSTR + t*4);
        a4.x += p.x; a4.y += p.y; a4.z += p.z; a4.w += p.w;
    }
    a4.x *= 0.0625f; a4.y *= 0.0625f; a4.z *= 0.0625f; a4.w *= 0.0625f;
    *(float4*)(avg + ((size_t)b*SEQ + q)*SEQ + t*4) = a4;
}

// ============================================================
// ctx = P(fp16) @ V(fp16 hi/lo): 3-stage cp.async, 2-pass (R13)
// ============================================================
__global__ __launch_bounds__(256, 2)
void ctx_mma(const __half* __restrict__ P, const __half* __restrict__ Vt2,
             __half* __restrict__ Cx)
{
    extern __shared__ __align__(16) uint32_t smw[];
    const uint32_t sb = (uint32_t)__cvta_generic_to_shared(smw);
    const int tid = threadIdx.x, wid = tid >> 5, lane = tid & 31;
    const int wm = (wid >> 2)*64, wn2 = (wid & 3)*16;
    const int bh = blockIdx.y, b = bh >> 4, h = bh & 15;
    const int bm = blockIdx.x*128;

    const int ar = tid >> 2, as = tid & 3;
    const __half* pA0 = P + (size_t)bh*SS + (size_t)(bm + ar)*SEQ + as*8;
    const __half* pA1 = P + (size_t)bh*SS + (size_t)(bm + ar + 64)*SEQ + as*8;
    const __half* pBh = Vt2 + ((size_t)b*EMB + h*DH + ar)*SEQ + as*8;

    const uint32_t wA0 = (ar*SKW + as*4)*4;
    const uint32_t wA1 = ((ar+64)*SKW + as*4)*4;
    const uint32_t wB  = (ar*SKW + as*4)*4;

    float acc[4][2][4];
#pragma unroll
    for (int i = 0; i < 4; i++)
#pragma unroll
        for (int j = 0; j < 2; j++)
#pragma unroll
            for (int k = 0; k < 4; k++) acc[i][j][k] = 0.f;

    auto issue = [&](int c){
        uint32_t bbuf = sb + (c % 3)*(CTX2BUF*4);
        size_t go = (size_t)c*32;
        cp16(bbuf + wA0, pA0 + go);
        cp16(bbuf + wA1, pA1 + go);
        cp16(bbuf + GPLANE*4 + wB, pBh + go);
        cp16(bbuf + (GPLANE + BPLN)*4 + wB, pBh + ACT + go);
        CP_COMMIT();
    };

    issue(0);
    issue(1);
    for (int c = 0; c < 32; c++){
        CP_WAIT1();
        __syncthreads();
        if (c + 2 < 32) issue(c + 2);
        uint32_t* cur = smw + (c % 3)*CTX2BUF;
        mma_chunk_h2<4,2>(acc, cur, cur + GPLANE, cur + GPLANE + BPLN, wm, wn2, lane);
    }

    const int r = lane >> 2, cl = (lane & 3)*2;
#pragma unroll
    for (int mi = 0; mi < 4; mi++){
#pragma unroll
        for (int ni = 0; ni < 2; ni++){
            int row = bm + wm + mi*16 + r;
            int col = h*DH + wn2 + ni*8 + cl;
            __half2 h0 = __floats2half2_rn(acc[mi][ni][0], acc[mi][ni][1]);
            __half2 h1 = __floats2half2_rn(acc[mi][ni][2], acc[mi][ni][3]);
            *(__half2*)(Cx + ((size_t)b*SEQ + row)*EMB + col)     = h0;
            *(__half2*)(Cx + ((size_t)b*SEQ + row + 8)*EMB + col) = h1;
        }
    }
}

// ============================================================
// V transpose fp16 -> fp16, both planes: z = plane*4 + b
// ============================================================
__global__ void transpose_k(const __half* __restrict__ Vr2, __half* __restrict__ Vt2)
{
    __shared__ __half tile[32][33];
    const int b = blockIdx.z & 3;
    const size_t pl = (size_t)(blockIdx.z >> 2)*ACT;
    const int e0 = blockIdx.x*32, s0 = blockIdx.y*32;
    const int tx = threadIdx.x, ty = threadIdx.y;
    const __half* src = Vr2 + pl + (size_t)b*SEQ*EMB;
#pragma unroll
    for (int i = 0; i < 32; i += 8)
        tile[ty + i][tx] = src[(size_t)(s0 + ty + i)*EMB + e0 + tx];
    __syncthreads();
#pragma unroll
    for (int i = 0; i < 32; i += 8)
        Vt2[pl + ((size_t)b*EMB + e0 + ty + i)*SEQ + s0 + tx] = tile[tx][ty + i];
}

// ============================================================
extern "C" void kernel_launch(void* const* d_in, const int* in_sizes, int n_in,
                              void* d_out, int out_size)
{
    const float* query = (const float*)d_in[0];
    const float* key   = (const float*)d_in[1];
    const float* value = (const float*)d_in[2];
    const int*   mask  = (const int*)  d_in[3];
    const float* Wq = (const float*)d_in[4];
    const float* bq = (const float*)d_in[5];
    const float* Wk = (const float*)d_in[6];
    const float* bk = (const float*)d_in[7];
    const float* Wv = (const float*)d_in[8];
    const float* bv = (const float*)d_in[9];
    const float* Wo = (const float*)d_in[10];
    const float* bo = (const float*)d_in[11];

    float* out      = (float*)d_out;
    float* attn_avg = out + ACT;

    float* ATT; __half *PRB, *VR2, *VT2;
    __half *QI, *KI, *VI, *WQ2, *WK2, *WV2, *WO2, *Q1, *K2;
    cudaGetSymbolAddress((void**)&ATT, g_attn);
    cudaGetSymbolAddress((void**)&PRB, g_probs);
    cudaGetSymbolAddress((void**)&QI,  g_qi);  cudaGetSymbolAddress((void**)&KI,  g_ki);
    cudaGetSymbolAddress((void**)&VI,  g_vi);
    cudaGetSymbolAddress((void**)&WQ2, g_Wq2); cudaGetSymbolAddress((void**)&WK2, g_Wk2);
    cudaGetSymbolAddress((void**)&WV2, g_Wv2); cudaGetSymbolAddress((void**)&WO2, g_Wo2);
    cudaGetSymbolAddress((void**)&Q1,  g_Q1);  cudaGetSymbolAddress((void**)&K2,  g_K2);
    cudaGetSymbolAddress((void**)&VR2, g_Vr2); cudaGetSymbolAddress((void**)&VT2, g_Vt2);
    __half* CTXH = Q1;

    const int SM_GEMMD = 3*GBUF*4;       // 92160
    const int SM_CTX2  = 3*CTX2BUF*4;    // 61440

    cudaFuncSetAttribute(gemm_qk,    cudaFuncAttributeMaxDynamicSharedMemorySize, SM_GEMMD);
    cudaFuncSetAttribute(gemm_out,   cudaFuncAttributeMaxDynamicSharedMemorySize, SM_GEMMD);
    cudaFuncSetAttribute(scores_mma, cudaFuncAttributeMaxDynamicSharedMemorySize, SM_SCOR);
    cudaFuncSetAttribute(ctx_mma,    cudaFuncAttributeMaxDynamicSharedMemorySize, SM_CTX2);
    cudaFuncSetAttribute(probs_vproj,cudaFuncAttributeMaxDynamicSharedMemorySize, SM_FUSE);

    const int M = BATCH*SEQ;
    const int nact8 = (int)(ACT/8), nw8 = (int)(EE/8);

    split_act<<<dim3((nact8+255)/256, 3), 256>>>(query, key, value, QI, KI, VI, nact8);
    split_w  <<<dim3((nw8+255)/256, 4), 256>>>(Wq, Wk, Wv, Wo, WQ2, WK2, WV2, WO2, nw8);

    gemm_qk<<<dim3(EMB/128, M/128, 2), 256, SM_GEMMD>>>(QI, KI, WQ2, WK2, bq, bk, Q1, K2);

    scores_mma<<<dim3(SEQ/128, SEQ/128, BH), 256, SM_SCOR>>>(Q1, K2, mask, ATT);

    probs_vproj<<<256 + BATCH*SEQ, 256, SM_FUSE>>>(ATT, attn_avg, PRB, VI, WV2, bv, VR2);

    transpose_k<<<dim3(EMB/32, SEQ/32, 2*BATCH), dim3(32, 8)>>>(VR2, VT2);

    ctx_mma<<<dim3(SEQ/128, BH), 256, SM_CTX2>>>(PRB, VT2, CTXH);

    gemm_out<<<dim3(EMB/128, M/128), 256, SM_GEMMD>>>(CTXH, WO2, bo, out);
}